// round 2
// baseline (speedup 1.0000x reference)
#include <cuda_runtime.h>
#include <math.h>

#define BB 4
#define CC 64
#define HH 96
#define WW 96
#define NN (HH*WW)
#define HP 48
#define WP 48
#define MM (HP*WP)
#define KD 64
#define OD 64

__device__ float g_xp [BB*CC*MM];
__device__ float g_c2p[BB*CC*MM];
__device__ float g_ea [BB*MM];
__device__ float g_kT [BB*MM*KD];
__device__ float g_vT [BB*MM*CC];
__device__ float g_qT [BB*NN*KD];

__global__ void pool_kernel(const float* __restrict__ x, const float* __restrict__ c2) {
    int idx = blockIdx.x * blockDim.x + threadIdx.x;
    if (idx >= BB*CC*MM) return;
    int mp = idx % MM;
    int bc = idx / MM;
    int hp = mp / WP, wp = mp % WP;
    int base = (bc*HH + 2*hp)*WW + 2*wp;
    float xv = fmaxf(fmaxf(x[base], x[base+1]), fmaxf(x[base+WW], x[base+WW+1]));
    g_xp[idx] = xv;
    g_c2p[idx] = fmaxf(fmaxf(c2[base], c2[base+1]), fmaxf(c2[base+WW], c2[base+WW+1]));
    int b = bc / CC, c = bc % CC;
    g_vT[(b*MM + mp)*CC + c] = xv;
}

__global__ void edge_kernel(const float* __restrict__ w_ea1,
                            const float* __restrict__ bn_w, const float* __restrict__ bn_b,
                            const float* __restrict__ bn_m, const float* __restrict__ bn_v,
                            const float* __restrict__ w_ea2, const float* __restrict__ b_ea2) {
    __shared__ __align__(16) float w1t[2*CC*OD];
    __shared__ float scs[OD], bbs[OD], w2s[OD];
    int tid = threadIdx.x;
    for (int i = tid; i < 2*CC*OD; i += blockDim.x) {
        int o = i % OD, c = i / OD;
        w1t[i] = w_ea1[o*2*CC + c];
    }
    if (tid < OD) {
        float sc = bn_w[tid] * rsqrtf(bn_v[tid] + 1e-5f);
        scs[tid] = sc;
        bbs[tid] = bn_b[tid] - bn_m[tid]*sc;
        w2s[tid] = w_ea2[tid];
    }
    __syncthreads();
    int pix = blockIdx.x * blockDim.x + tid;
    if (pix >= BB*MM) return;
    int b = pix / MM, mp = pix % MM;
    float4 h4[OD/4];
    #pragma unroll
    for (int i = 0; i < OD/4; i++) h4[i] = make_float4(0.f,0.f,0.f,0.f);
    const float* c2p = g_c2p + b*CC*MM + mp;
    const float* xpp = g_xp  + b*CC*MM + mp;
    for (int c = 0; c < 2*CC; c++) {
        float xv = (c < CC) ? c2p[c*MM] : xpp[(c-CC)*MM];
        const float4* wr = (const float4*)(w1t + c*OD);
        #pragma unroll
        for (int i = 0; i < OD/4; i++) {
            float4 wv = wr[i];
            h4[i].x = fmaf(wv.x, xv, h4[i].x);
            h4[i].y = fmaf(wv.y, xv, h4[i].y);
            h4[i].z = fmaf(wv.z, xv, h4[i].z);
            h4[i].w = fmaf(wv.w, xv, h4[i].w);
        }
    }
    float logit = b_ea2[0];
    const float* h = (const float*)h4;
    #pragma unroll
    for (int o = 0; o < OD; o++) {
        float hv = fmaxf(fmaf(h[o], scs[o], bbs[o]), 0.f);
        logit = fmaf(w2s[o], hv, logit);
    }
    g_ea[pix] = 1.f / (1.f + expf(-logit));
}

// is_q=1: in = x (extern), out = g_qT, npix = NN
// is_q=0: in = g_xp,       out = g_kT, npix = MM
__global__ void conv1x1_kernel(const float* __restrict__ xin,
                               const float* __restrict__ wq,
                               const float* __restrict__ bq,
                               int npix, int is_q) {
    __shared__ __align__(16) float wt[CC*KD];
    __shared__ float bs[KD];
    int tid = threadIdx.x;
    for (int i = tid; i < CC*KD; i += blockDim.x) {
        int k = i % KD, c = i / KD;
        wt[i] = wq[k*CC + c];
    }
    if (tid < KD) bs[tid] = bq[tid];
    __syncthreads();
    int idx = blockIdx.x * blockDim.x + tid;
    if (idx >= BB*npix) return;
    int b = idx / npix, n = idx % npix;
    const float* in = is_q ? xin : (const float*)g_xp;
    float4 acc4[KD/4];
    const float4* bsv = (const float4*)bs;
    #pragma unroll
    for (int i = 0; i < KD/4; i++) acc4[i] = bsv[i];
    const float* ip = in + b*CC*npix + n;
    for (int c = 0; c < CC; c++) {
        float xv = ip[c*npix];
        const float4* wr = (const float4*)(wt + c*KD);
        #pragma unroll
        for (int i = 0; i < KD/4; i++) {
            float4 wv = wr[i];
            acc4[i].x = fmaf(wv.x, xv, acc4[i].x);
            acc4[i].y = fmaf(wv.y, xv, acc4[i].y);
            acc4[i].z = fmaf(wv.z, xv, acc4[i].z);
            acc4[i].w = fmaf(wv.w, xv, acc4[i].w);
        }
    }
    float4* op = (float4*)((is_q ? g_qT : g_kT) + (size_t)idx*KD);
    #pragma unroll
    for (int i = 0; i < KD/4; i++) op[i] = acc4[i];
}

#define TQ 128
#define MC 64

__global__ __launch_bounds__(TQ) void attn_kernel(const float* __restrict__ x,
                                                  const float* __restrict__ gamma,
                                                  float* __restrict__ out) {
    __shared__ __align__(16) float Ks[MC*KD];
    __shared__ __align__(16) float Vs[MC*CC];
    __shared__ float eas[MC];
    int tid = threadIdx.x;
    int b = blockIdx.y;
    int n = blockIdx.x * TQ + tid;

    float4 q4[KD/4];
    const float4* qp = (const float4*)(g_qT + ((size_t)b*NN + n)*KD);
    #pragma unroll
    for (int i = 0; i < KD/4; i++) q4[i] = qp[i];

    float4 acc4[CC/4];
    #pragma unroll
    for (int i = 0; i < CC/4; i++) acc4[i] = make_float4(0.f,0.f,0.f,0.f);
    float rmax = -1e30f, lsum = 0.f;

    for (int m0 = 0; m0 < MM; m0 += MC) {
        __syncthreads();
        const float4* kg = (const float4*)(g_kT + ((size_t)b*MM + m0)*KD);
        const float4* vg = (const float4*)(g_vT + ((size_t)b*MM + m0)*CC);
        float4* Ks4 = (float4*)Ks;
        float4* Vs4 = (float4*)Vs;
        #pragma unroll
        for (int i = 0; i < (MC*KD/4)/TQ; i++) {
            Ks4[tid + i*TQ] = kg[tid + i*TQ];
            Vs4[tid + i*TQ] = vg[tid + i*TQ];
        }
        if (tid < MC) eas[tid] = g_ea[b*MM + m0 + tid];
        __syncthreads();

        for (int mm = 0; mm < MC; mm++) {
            const float4* kr = (const float4*)(Ks + mm*KD);
            float s0=0.f, s1=0.f, s2=0.f, s3=0.f;
            #pragma unroll
            for (int i = 0; i < KD/4; i++) {
                float4 kv = kr[i];
                s0 = fmaf(q4[i].x, kv.x, s0);
                s1 = fmaf(q4[i].y, kv.y, s1);
                s2 = fmaf(q4[i].z, kv.z, s2);
                s3 = fmaf(q4[i].w, kv.w, s3);
            }
            float s = ((s0+s1)+(s2+s3)) * eas[mm];
            if (s > rmax) {
                float corr = __expf(rmax - s);
                lsum *= corr;
                #pragma unroll
                for (int i = 0; i < CC/4; i++) {
                    acc4[i].x *= corr; acc4[i].y *= corr;
                    acc4[i].z *= corr; acc4[i].w *= corr;
                }
                rmax = s;
            }
            float p = __expf(s - rmax);
            lsum += p;
            const float4* vr = (const float4*)(Vs + mm*CC);
            #pragma unroll
            for (int i = 0; i < CC/4; i++) {
                float4 vv = vr[i];
                acc4[i].x = fmaf(p, vv.x, acc4[i].x);
                acc4[i].y = fmaf(p, vv.y, acc4[i].y);
                acc4[i].z = fmaf(p, vv.z, acc4[i].z);
                acc4[i].w = fmaf(p, vv.w, acc4[i].w);
            }
        }
    }

    float inv = gamma[0] / lsum;
    #pragma unroll
    for (int i = 0; i < CC/4; i++) {
        int c = 4*i;
        size_t o0 = ((size_t)(b*CC + c    ))*NN + n;
        size_t o1 = ((size_t)(b*CC + c + 1))*NN + n;
        size_t o2 = ((size_t)(b*CC + c + 2))*NN + n;
        size_t o3 = ((size_t)(b*CC + c + 3))*NN + n;
        out[o0] = fmaf(acc4[i].x, inv, x[o0]);
        out[o1] = fmaf(acc4[i].y, inv, x[o1]);
        out[o2] = fmaf(acc4[i].z, inv, x[o2]);
        out[o3] = fmaf(acc4[i].w, inv, x[o3]);
    }
}

extern "C" void kernel_launch(void* const* d_in, const int* in_sizes, int n_in,
                              void* d_out, int out_size) {
    const float* c2    = (const float*)d_in[0];
    const float* x     = (const float*)d_in[1];
    const float* w_ea1 = (const float*)d_in[2];
    const float* bn_w  = (const float*)d_in[3];
    const float* bn_b  = (const float*)d_in[4];
    const float* bn_m  = (const float*)d_in[5];
    const float* bn_v  = (const float*)d_in[6];
    const float* w_ea2 = (const float*)d_in[7];
    const float* b_ea2 = (const float*)d_in[8];
    const float* w_q   = (const float*)d_in[9];
    const float* b_q   = (const float*)d_in[10];
    const float* gamma = (const float*)d_in[11];
    float* out = (float*)d_out;

    pool_kernel<<<(BB*CC*MM + 255)/256, 256>>>(x, c2);
    edge_kernel<<<(BB*MM + 255)/256, 256>>>(w_ea1, bn_w, bn_b, bn_m, bn_v, w_ea2, b_ea2);
    conv1x1_kernel<<<(BB*NN + 255)/256, 256>>>(x, w_q, b_q, NN, 1);
    conv1x1_kernel<<<(BB*MM + 255)/256, 256>>>(x, w_q, b_q, MM, 0);
    attn_kernel<<<dim3(NN/TQ, BB), TQ>>>(x, gamma, out);
}

// round 3
// speedup vs baseline: 1.0098x; 1.0098x over previous
#include <cuda_runtime.h>
#include <math.h>

#define BB 4
#define CC 64
#define HH 96
#define WW 96
#define NN (HH*WW)
#define HP 48
#define WP 48
#define MM (HP*WP)
#define KD 64
#define OD 64

typedef unsigned long long u64;

// ---- packed f32x2 helpers (FFMA2: only reachable via PTX fma.rn.f32x2) ------
__device__ __forceinline__ u64 fma2(u64 a, u64 b, u64 c) {
    u64 d;
    asm("fma.rn.f32x2 %0, %1, %2, %3;" : "=l"(d) : "l"(a), "l"(b), "l"(c));
    return d;
}
__device__ __forceinline__ u64 mul2(u64 a, u64 b) {
    u64 d;
    asm("mul.rn.f32x2 %0, %1, %2;" : "=l"(d) : "l"(a), "l"(b));
    return d;
}
__device__ __forceinline__ u64 pack2(float lo, float hi) {
    u64 d;
    asm("mov.b64 %0, {%1, %2};" : "=l"(d) : "f"(lo), "f"(hi));
    return d;
}
__device__ __forceinline__ float2 unpack2(u64 v) {
    float2 r;
    asm("mov.b64 {%0, %1}, %2;" : "=f"(r.x), "=f"(r.y) : "l"(v));
    return r;
}

__device__ float g_xp [BB*CC*MM];
__device__ float g_c2p[BB*CC*MM];
__device__ float g_ea [BB*MM];
__device__ float g_kT [BB*MM*KD];
__device__ float g_vT [BB*MM*CC];
__device__ float g_qT [BB*NN*KD];

// ---------------- K1: 2x2 maxpool; also write V transposed -------------------
__global__ void pool_kernel(const float* __restrict__ x, const float* __restrict__ c2) {
    int idx = blockIdx.x * blockDim.x + threadIdx.x;
    if (idx >= BB*CC*MM) return;
    int mp = idx % MM;
    int bc = idx / MM;
    int hp = mp / WP, wp = mp % WP;
    int base = (bc*HH + 2*hp)*WW + 2*wp;
    float xv = fmaxf(fmaxf(x[base], x[base+1]), fmaxf(x[base+WW], x[base+WW+1]));
    g_xp[idx] = xv;
    g_c2p[idx] = fmaxf(fmaxf(c2[base], c2[base+1]), fmaxf(c2[base+WW], c2[base+WW+1]));
    int b = bc / CC, c = bc % CC;
    g_vT[(b*MM + mp)*CC + c] = xv;
}

// ---------------- K2: edge attention gate (64-thr blocks, packed FMA) --------
__global__ __launch_bounds__(64) void edge_kernel(
        const float* __restrict__ w_ea1,
        const float* __restrict__ bn_w, const float* __restrict__ bn_b,
        const float* __restrict__ bn_m, const float* __restrict__ bn_v,
        const float* __restrict__ w_ea2, const float* __restrict__ b_ea2) {
    __shared__ __align__(16) float w1t[2*CC*OD];   // transposed [c][o]
    __shared__ float scs[OD], bbs[OD], w2s[OD];
    int tid = threadIdx.x;
    for (int i = tid; i < 2*CC*OD; i += 64) {
        int o = i % OD, c = i / OD;
        w1t[i] = w_ea1[o*2*CC + c];
    }
    if (tid < OD) {
        float sc = bn_w[tid] * rsqrtf(bn_v[tid] + 1e-5f);
        scs[tid] = sc;
        bbs[tid] = bn_b[tid] - bn_m[tid]*sc;
        w2s[tid] = w_ea2[tid];
    }
    __syncthreads();
    int pix = blockIdx.x * 64 + tid;
    if (pix >= BB*MM) return;
    int b = pix / MM, mp = pix % MM;
    u64 h2[OD/2];
    #pragma unroll
    for (int i = 0; i < OD/2; i++) h2[i] = 0ull;
    const float* c2p = g_c2p + b*CC*MM + mp;
    const float* xpp = g_xp  + b*CC*MM + mp;
    for (int c = 0; c < 2*CC; c++) {
        float xv = (c < CC) ? c2p[c*MM] : xpp[(c-CC)*MM];
        u64 xx = pack2(xv, xv);
        const u64* wr = (const u64*)(w1t + c*OD);
        #pragma unroll
        for (int i = 0; i < OD/2; i++) h2[i] = fma2(xx, wr[i], h2[i]);
    }
    float logit = b_ea2[0];
    #pragma unroll
    for (int i = 0; i < OD/2; i++) {
        float2 hv = unpack2(h2[i]);
        int o = 2*i;
        float a = fmaxf(fmaf(hv.x, scs[o],   bbs[o]),   0.f);
        float bq = fmaxf(fmaf(hv.y, scs[o+1], bbs[o+1]), 0.f);
        logit = fmaf(w2s[o], a, logit);
        logit = fmaf(w2s[o+1], bq, logit);
    }
    g_ea[pix] = 1.f / (1.f + expf(-logit));
}

// ---------------- K3: 1x1 conv (shared w_q), 64 pixels x 2 k-halves ----------
__global__ __launch_bounds__(128) void conv1x1_kernel(
        const float* __restrict__ xin, const float* __restrict__ wq,
        const float* __restrict__ bq, int npix, int is_q) {
    __shared__ __align__(16) float wt[CC*KD];      // [c][k]
    __shared__ __align__(16) float bs[KD];
    int tid = threadIdx.x;                          // 0..127
    for (int i = tid; i < CC*KD; i += 128) {
        int k = i % KD, c = i / KD;
        wt[i] = wq[k*CC + c];
    }
    if (tid < KD) bs[tid] = bq[tid];
    __syncthreads();
    int kh = tid >> 6;                              // k-half 0/1
    int p  = blockIdx.x * 64 + (tid & 63);          // pixel index over B*npix
    if (p >= BB*npix) return;
    int b = p / npix, n = p % npix;
    const float* in = is_q ? xin : (const float*)g_xp;
    const float* ip = in + b*CC*npix + n;
    u64 acc[16];
    const u64* bsp = (const u64*)(bs + kh*32);
    #pragma unroll
    for (int i = 0; i < 16; i++) acc[i] = bsp[i];
    for (int c = 0; c < CC; c++) {
        float xv = ip[c*npix];
        u64 xx = pack2(xv, xv);
        const u64* wr = (const u64*)(wt + c*KD + kh*32);
        #pragma unroll
        for (int i = 0; i < 16; i++) acc[i] = fma2(xx, wr[i], acc[i]);
    }
    u64* op = (u64*)((is_q ? g_qT : g_kT) + (size_t)p*KD + kh*32);
    #pragma unroll
    for (int i = 0; i < 16; i++) op[i] = acc[i];
}

// ---------------- K4: flash attention (packed f32x2 math) --------------------
#define TQ 128
#define MC 64

__global__ __launch_bounds__(TQ) void attn_kernel(const float* __restrict__ x,
                                                  const float* __restrict__ gamma,
                                                  float* __restrict__ out) {
    __shared__ __align__(16) float Ks[MC*KD];
    __shared__ __align__(16) float Vs[MC*CC];
    __shared__ float eas[MC];
    int tid = threadIdx.x;
    int b = blockIdx.y;
    int n = blockIdx.x * TQ + tid;

    u64 q2[KD/2];                                   // 32 packed q pairs
    {
        const ulonglong2* qp = (const ulonglong2*)(g_qT + ((size_t)b*NN + n)*KD);
        #pragma unroll
        for (int i = 0; i < KD/4; i++) {
            ulonglong2 v = qp[i];
            q2[2*i]   = v.x;
            q2[2*i+1] = v.y;
        }
    }

    u64 acc[CC/2];                                  // 32 packed channel pairs
    #pragma unroll
    for (int i = 0; i < CC/2; i++) acc[i] = 0ull;
    float rmax = -1e30f, lsum = 0.f;

    for (int m0 = 0; m0 < MM; m0 += MC) {
        __syncthreads();
        const float4* kg = (const float4*)(g_kT + ((size_t)b*MM + m0)*KD);
        const float4* vg = (const float4*)(g_vT + ((size_t)b*MM + m0)*CC);
        float4* Ks4 = (float4*)Ks;
        float4* Vs4 = (float4*)Vs;
        #pragma unroll
        for (int i = 0; i < (MC*KD/4)/TQ; i++) {
            Ks4[tid + i*TQ] = kg[tid + i*TQ];
            Vs4[tid + i*TQ] = vg[tid + i*TQ];
        }
        if (tid < MC) eas[tid] = g_ea[b*MM + m0 + tid];
        __syncthreads();

        for (int mm = 0; mm < MC; mm++) {
            const u64* kr = (const u64*)(Ks + mm*KD);
            u64 s0 = 0ull, s1 = 0ull, s2 = 0ull, s3 = 0ull;
            #pragma unroll
            for (int i = 0; i < KD/8; i++) {        // 8 iters x 4 packed FMA
                s0 = fma2(q2[4*i],   kr[4*i],   s0);
                s1 = fma2(q2[4*i+1], kr[4*i+1], s1);
                s2 = fma2(q2[4*i+2], kr[4*i+2], s2);
                s3 = fma2(q2[4*i+3], kr[4*i+3], s3);
            }
            float2 f0 = unpack2(s0), f1 = unpack2(s1);
            float2 f2 = unpack2(s2), f3 = unpack2(s3);
            float s = ((f0.x+f0.y)+(f1.x+f1.y)) + ((f2.x+f2.y)+(f3.x+f3.y));
            s *= eas[mm];
            if (s > rmax) {                          // rare lazy rescale
                float corr = __expf(rmax - s);
                lsum *= corr;
                u64 cc2 = pack2(corr, corr);
                #pragma unroll
                for (int i = 0; i < CC/2; i++) acc[i] = mul2(acc[i], cc2);
                rmax = s;
            }
            float p = __expf(s - rmax);
            lsum += p;
            u64 pp = pack2(p, p);
            const u64* vr = (const u64*)(Vs + mm*CC);
            #pragma unroll
            for (int i = 0; i < CC/2; i++) acc[i] = fma2(pp, vr[i], acc[i]);
        }
    }

    float inv = gamma[0] / lsum;
    #pragma unroll
    for (int i = 0; i < CC/2; i++) {
        float2 a = unpack2(acc[i]);
        int c = 2*i;
        size_t o0 = ((size_t)(b*CC + c    ))*NN + n;
        size_t o1 = ((size_t)(b*CC + c + 1))*NN + n;
        out[o0] = fmaf(a.x, inv, x[o0]);
        out[o1] = fmaf(a.y, inv, x[o1]);
    }
}

// ---------------- launch ------------------------------------------------------
extern "C" void kernel_launch(void* const* d_in, const int* in_sizes, int n_in,
                              void* d_out, int out_size) {
    const float* c2    = (const float*)d_in[0];
    const float* x     = (const float*)d_in[1];
    const float* w_ea1 = (const float*)d_in[2];
    const float* bn_w  = (const float*)d_in[3];
    const float* bn_b  = (const float*)d_in[4];
    const float* bn_m  = (const float*)d_in[5];
    const float* bn_v  = (const float*)d_in[6];
    const float* w_ea2 = (const float*)d_in[7];
    const float* b_ea2 = (const float*)d_in[8];
    const float* w_q   = (const float*)d_in[9];
    const float* b_q   = (const float*)d_in[10];
    const float* gamma = (const float*)d_in[11];
    float* out = (float*)d_out;

    pool_kernel<<<(BB*CC*MM + 255)/256, 256>>>(x, c2);
    edge_kernel<<<(BB*MM + 63)/64, 64>>>(w_ea1, bn_w, bn_b, bn_m, bn_v, w_ea2, b_ea2);
    conv1x1_kernel<<<(BB*NN + 63)/64, 128>>>(x, w_q, b_q, NN, 1);
    conv1x1_kernel<<<(BB*MM + 63)/64, 128>>>(x, w_q, b_q, MM, 0);
    attn_kernel<<<dim3(NN/TQ, BB), TQ>>>(x, gamma, out);
}

// round 7
// speedup vs baseline: 2.2727x; 2.2507x over previous
#include <cuda_runtime.h>
#include <math.h>
#include <stdint.h>

#define BB 4
#define CC 64
#define HH 96
#define WW 96
#define NN (HH*WW)
#define HP 48
#define WP 48
#define MM (HP*WP)
#define KD 64
#define OD 64

// ================= scratch =================
__device__ float g_xp [BB*CC*MM];   // pooled x  [b][c][m]  (V source)
__device__ float g_c2p[BB*CC*MM];
__device__ float g_ea [BB*MM];
__device__ float g_kT [BB*MM*KD];   // keys    [b][m][k]
__device__ float g_qT [BB*NN*KD];   // queries [b][n][k]

// ================= helpers =================
__device__ __forceinline__ uint32_t f2tf(float x) {       // round-to-nearest tf32
    uint32_t r;
    asm("cvt.rna.tf32.f32 %0, %1;" : "=r"(r) : "f"(x));
    return r;
}
__device__ __forceinline__ void mma8(float* d, const uint32_t* a, const uint32_t* b) {
    asm volatile("mma.sync.aligned.m16n8k8.row.col.f32.tf32.tf32.f32 "
        "{%0,%1,%2,%3}, {%4,%5,%6,%7}, {%8,%9}, {%0,%1,%2,%3};"
        : "+f"(d[0]), "+f"(d[1]), "+f"(d[2]), "+f"(d[3])
        : "r"(a[0]), "r"(a[1]), "r"(a[2]), "r"(a[3]), "r"(b[0]), "r"(b[1]));
}

// ================= K1: pool =================
__global__ void pool_kernel(const float* __restrict__ x, const float* __restrict__ c2) {
    int idx = blockIdx.x * blockDim.x + threadIdx.x;
    if (idx >= BB*CC*MM) return;
    int mp = idx % MM;
    int bc = idx / MM;
    int hp = mp / WP, wp = mp % WP;
    int base = (bc*HH + 2*hp)*WW + 2*wp;
    g_xp[idx]  = fmaxf(fmaxf(x[base],  x[base+1]),  fmaxf(x[base+WW],  x[base+WW+1]));
    g_c2p[idx] = fmaxf(fmaxf(c2[base], c2[base+1]), fmaxf(c2[base+WW], c2[base+WW+1]));
}

// ================= K2: edge gate =================
__global__ __launch_bounds__(64) void edge_kernel(
        const float* __restrict__ w_ea1,
        const float* __restrict__ bn_w, const float* __restrict__ bn_b,
        const float* __restrict__ bn_m, const float* __restrict__ bn_v,
        const float* __restrict__ w_ea2, const float* __restrict__ b_ea2) {
    __shared__ __align__(16) float w1t[2*CC*OD];
    __shared__ float scs[OD], bbs[OD], w2s[OD];
    int tid = threadIdx.x;
    for (int i = tid; i < 2*CC*OD; i += 64) {
        int o = i % OD, c = i / OD;
        w1t[i] = w_ea1[o*2*CC + c];
    }
    if (tid < OD) {
        float sc = bn_w[tid] * rsqrtf(bn_v[tid] + 1e-5f);
        scs[tid] = sc;
        bbs[tid] = bn_b[tid] - bn_m[tid]*sc;
        w2s[tid] = w_ea2[tid];
    }
    __syncthreads();
    int pix = blockIdx.x * 64 + tid;
    if (pix >= BB*MM) return;
    int b = pix / MM, mp = pix % MM;
    float h[OD];
    #pragma unroll
    for (int i = 0; i < OD; i++) h[i] = 0.f;
    const float* c2p = g_c2p + b*CC*MM + mp;
    const float* xpp = g_xp  + b*CC*MM + mp;
    for (int c = 0; c < 2*CC; c++) {
        float xv = (c < CC) ? c2p[c*MM] : xpp[(c-CC)*MM];
        const float* wr = w1t + c*OD;
        #pragma unroll
        for (int i = 0; i < OD; i++) h[i] = fmaf(wr[i], xv, h[i]);
    }
    float logit = b_ea2[0];
    #pragma unroll
    for (int o = 0; o < OD; o++) {
        float hv = fmaxf(fmaf(h[o], scs[o], bbs[o]), 0.f);
        logit = fmaf(w2s[o], hv, logit);
    }
    g_ea[pix] = 1.f / (1.f + expf(-logit));
}

// ================= K3: 1x1 conv =================
__global__ __launch_bounds__(128) void conv1x1_kernel(
        const float* __restrict__ xin, const float* __restrict__ wq,
        const float* __restrict__ bq, int npix, int is_q) {
    __shared__ __align__(16) float wt[CC*KD];
    __shared__ __align__(16) float bs[KD];
    int tid = threadIdx.x;
    for (int i = tid; i < CC*KD; i += 128) {
        int k = i % KD, c = i / KD;
        wt[i] = wq[k*CC + c];
    }
    if (tid < KD) bs[tid] = bq[tid];
    __syncthreads();
    int kh = tid >> 6;
    int p  = blockIdx.x * 64 + (tid & 63);
    if (p >= BB*npix) return;
    int b = p / npix, n = p % npix;
    const float* in = is_q ? xin : (const float*)g_xp;
    const float* ip = in + b*CC*npix + n;
    float4 acc[8];
    const float4* bsp = (const float4*)(bs + kh*32);
    #pragma unroll
    for (int i = 0; i < 8; i++) acc[i] = bsp[i];
    for (int c = 0; c < CC; c++) {
        float xv = ip[c*npix];
        const float4* wr = (const float4*)(wt + c*KD + kh*32);
        #pragma unroll
        for (int i = 0; i < 8; i++) {
            float4 wv = wr[i];
            acc[i].x = fmaf(wv.x, xv, acc[i].x);
            acc[i].y = fmaf(wv.y, xv, acc[i].y);
            acc[i].z = fmaf(wv.z, xv, acc[i].z);
            acc[i].w = fmaf(wv.w, xv, acc[i].w);
        }
    }
    float4* op = (float4*)((is_q ? g_qT : g_kT) + (size_t)p*KD + kh*32);
    #pragma unroll
    for (int i = 0; i < 8; i++) op[i] = acc[i];
}

// ================= K4: tf32 mma.sync flash attention =================
#define TILE 64
#define NT (MM/TILE)        /* 36 */
#define QPAD 68
#define KPAD 68
#define VPAD 68
#define PPAD 68
// float offsets in dynamic smem
#define SQ 0
#define SK (SQ + 128*QPAD)          /* 8704  */
#define SV (SK + TILE*KPAD)         /* 13056 */
#define SP (SV + CC*VPAD)           /* 17408 */
#define SEA (SP + 128*PPAD)         /* 26112 */
#define SMF (SEA + TILE)            /* 26176 floats = 104704 B */

__global__ __launch_bounds__(128, 2) void attn_mma_kernel(
        const float* __restrict__ x, const float* __restrict__ gamma,
        float* __restrict__ out) {
    extern __shared__ float sm[];
    float* Qsm = sm + SQ;
    float* Ksm = sm + SK;
    float* Vsm = sm + SV;
    float* Psm = sm + SP;
    float* easm = sm + SEA;

    int tid = threadIdx.x;
    int w = tid >> 5, lane = tid & 31;
    int g = lane >> 2, q = lane & 3;
    int b = blockIdx.y;
    int q0 = blockIdx.x * 128;

    // ---- Q fill (once) ----
    #pragma unroll
    for (int i = 0; i < 16; i++) {
        int idx = tid + i*128;
        int row = idx >> 4;
        int c4 = (idx & 15) * 4;
        *(float4*)(Qsm + row*QPAD + c4) =
            *(const float4*)(g_qT + ((size_t)(b*NN + q0 + row))*KD + c4);
    }

    float dacc[8][2][4];
    #pragma unroll
    for (int n = 0; n < 8; n++)
        #pragma unroll
        for (int m = 0; m < 2; m++)
            #pragma unroll
            for (int j = 0; j < 4; j++) dacc[n][m][j] = 0.f;
    float rs[4] = {0.f, 0.f, 0.f, 0.f};

    for (int t = 0; t < NT; t++) {
        int m0 = t * TILE;
        __syncthreads();   // prev tile's readers done with Ksm/Vsm

        // ---- K fill: Ksm[key][kd] ----
        #pragma unroll
        for (int i = 0; i < 8; i++) {
            int idx = tid + i*128;
            int key = idx >> 4;
            int c4 = (idx & 15) * 4;
            *(float4*)(Ksm + key*KPAD + c4) =
                *(const float4*)(g_kT + ((size_t)(b*MM + m0 + key))*KD + c4);
        }
        // ---- V fill: Vsm[ch][key], pre-converted tf32 ----
        #pragma unroll
        for (int i = 0; i < 8; i++) {
            int idx = tid + i*128;
            int ch = idx >> 4;
            int k4 = (idx & 15) * 4;
            float4 v = *(const float4*)(g_xp + ((size_t)(b*CC + ch))*MM + m0 + k4);
            uint4 tv;
            tv.x = f2tf(v.x); tv.y = f2tf(v.y); tv.z = f2tf(v.z); tv.w = f2tf(v.w);
            *(uint4*)(Vsm + ch*VPAD + k4) = tv;
        }
        if (tid < TILE) easm[tid] = g_ea[b*MM + m0 + tid];
        __syncthreads();

        // ---- QK: E = Qhi*Khi + Qlo*Khi + Qhi*Klo ----
        float eacc[8][2][4];
        #pragma unroll
        for (int n = 0; n < 8; n++)
            #pragma unroll
            for (int m = 0; m < 2; m++)
                #pragma unroll
                for (int j = 0; j < 4; j++) eacc[n][m][j] = 0.f;

        #pragma unroll
        for (int kc = 0; kc < 8; kc++) {
            uint32_t ah[2][4], al[2][4];
            #pragma unroll
            for (int m = 0; m < 2; m++) {
                int r = w*32 + m*16 + g;
                float x0 = Qsm[r*QPAD     + kc*8 + q];
                float x1 = Qsm[(r+8)*QPAD + kc*8 + q];
                float x2 = Qsm[r*QPAD     + kc*8 + q + 4];
                float x3 = Qsm[(r+8)*QPAD + kc*8 + q + 4];
                ah[m][0] = f2tf(x0); al[m][0] = f2tf(x0 - __uint_as_float(ah[m][0]));
                ah[m][1] = f2tf(x1); al[m][1] = f2tf(x1 - __uint_as_float(ah[m][1]));
                ah[m][2] = f2tf(x2); al[m][2] = f2tf(x2 - __uint_as_float(ah[m][2]));
                ah[m][3] = f2tf(x3); al[m][3] = f2tf(x3 - __uint_as_float(ah[m][3]));
            }
            #pragma unroll
            for (int n = 0; n < 8; n++) {
                int key = n*8 + g;
                float k0 = Ksm[key*KPAD + kc*8 + q];
                float k1 = Ksm[key*KPAD + kc*8 + q + 4];
                uint32_t bh[2], bl[2];
                bh[0] = f2tf(k0); bl[0] = f2tf(k0 - __uint_as_float(bh[0]));
                bh[1] = f2tf(k1); bl[1] = f2tf(k1 - __uint_as_float(bh[1]));
                #pragma unroll
                for (int m = 0; m < 2; m++) {
                    mma8(eacc[n][m], ah[m], bh);
                    mma8(eacc[n][m], al[m], bh);
                    mma8(eacc[n][m], ah[m], bl);
                }
            }
        }

        // ---- softmax (no max-shift) + P store (tf32) ----
        #pragma unroll
        for (int n = 0; n < 8; n++) {
            float2 ea2 = *(float2*)(easm + n*8 + 2*q);
            #pragma unroll
            for (int m = 0; m < 2; m++) {
                float p0 = __expf(eacc[n][m][0] * ea2.x);
                float p1 = __expf(eacc[n][m][1] * ea2.y);
                float p2 = __expf(eacc[n][m][2] * ea2.x);
                float p3 = __expf(eacc[n][m][3] * ea2.y);
                rs[m*2+0] += p0 + p1;
                rs[m*2+1] += p2 + p3;
                int r = w*32 + m*16 + g;
                uint2 lo = make_uint2(f2tf(p0), f2tf(p1));
                uint2 hi = make_uint2(f2tf(p2), f2tf(p3));
                *(uint2*)(Psm + r*PPAD     + n*8 + 2*q) = lo;
                *(uint2*)(Psm + (r+8)*PPAD + n*8 + 2*q) = hi;
            }
        }
        __syncwarp();

        // ---- PV: D += P * V ----
        #pragma unroll
        for (int kc = 0; kc < 8; kc++) {
            uint32_t pa[2][4];
            #pragma unroll
            for (int m = 0; m < 2; m++) {
                int r = w*32 + m*16 + g;
                pa[m][0] = __float_as_uint(Psm[r*PPAD     + kc*8 + q]);
                pa[m][1] = __float_as_uint(Psm[(r+8)*PPAD + kc*8 + q]);
                pa[m][2] = __float_as_uint(Psm[r*PPAD     + kc*8 + q + 4]);
                pa[m][3] = __float_as_uint(Psm[(r+8)*PPAD + kc*8 + q + 4]);
            }
            #pragma unroll
            for (int n = 0; n < 8; n++) {
                uint32_t vb[2];
                vb[0] = __float_as_uint(Vsm[(n*8+g)*VPAD + kc*8 + q]);
                vb[1] = __float_as_uint(Vsm[(n*8+g)*VPAD + kc*8 + q + 4]);
                #pragma unroll
                for (int m = 0; m < 2; m++) mma8(dacc[n][m], pa[m], vb);
            }
        }
    }

    // ---- epilogue: quad-reduce row sums, normalize, residual add ----
    #pragma unroll
    for (int i = 0; i < 4; i++) {
        rs[i] += __shfl_xor_sync(0xFFFFFFFFu, rs[i], 1);
        rs[i] += __shfl_xor_sync(0xFFFFFFFFu, rs[i], 2);
    }
    float gm = gamma[0];
    float invA0 = gm / rs[0], invB0 = gm / rs[1];   // m=0: row g, row g+8
    float invA1 = gm / rs[2], invB1 = gm / rs[3];   // m=1
    #pragma unroll
    for (int n = 0; n < 8; n++) {
        #pragma unroll
        for (int m = 0; m < 2; m++) {
            int ch = n*8 + 2*q;
            int r  = w*32 + m*16 + g;
            float ia = m ? invA1 : invA0;
            float ib = m ? invB1 : invB0;
            size_t o00 = ((size_t)(b*CC + ch))*NN + q0 + r;
            size_t o01 = o00 + NN;
            size_t o10 = o00 + 8;
            size_t o11 = o01 + 8;
            out[o00] = fmaf(dacc[n][m][0], ia, x[o00]);
            out[o01] = fmaf(dacc[n][m][1], ia, x[o01]);
            out[o10] = fmaf(dacc[n][m][2], ib, x[o10]);
            out[o11] = fmaf(dacc[n][m][3], ib, x[o11]);
        }
    }
}

// ================= launch =================
extern "C" void kernel_launch(void* const* d_in, const int* in_sizes, int n_in,
                              void* d_out, int out_size) {
    const float* c2    = (const float*)d_in[0];
    const float* x     = (const float*)d_in[1];
    const float* w_ea1 = (const float*)d_in[2];
    const float* bn_w  = (const float*)d_in[3];
    const float* bn_b  = (const float*)d_in[4];
    const float* bn_m  = (const float*)d_in[5];
    const float* bn_v  = (const float*)d_in[6];
    const float* w_ea2 = (const float*)d_in[7];
    const float* b_ea2 = (const float*)d_in[8];
    const float* w_q   = (const float*)d_in[9];
    const float* b_q   = (const float*)d_in[10];
    const float* gamma = (const float*)d_in[11];
    float* out = (float*)d_out;

    cudaFuncSetAttribute(attn_mma_kernel,
                         cudaFuncAttributeMaxDynamicSharedMemorySize, SMF*4);

    pool_kernel<<<(BB*CC*MM + 255)/256, 256>>>(x, c2);
    edge_kernel<<<(BB*MM + 63)/64, 64>>>(w_ea1, bn_w, bn_b, bn_m, bn_v, w_ea2, b_ea2);
    conv1x1_kernel<<<(BB*NN + 63)/64, 128>>>(x, w_q, b_q, NN, 1);
    conv1x1_kernel<<<(BB*MM + 63)/64, 128>>>(x, w_q, b_q, MM, 0);
    attn_mma_kernel<<<dim3(NN/128, BB), 128, SMF*4>>>(x, gamma, out);
}

// round 8
// speedup vs baseline: 2.7811x; 1.2237x over previous
#include <cuda_runtime.h>
#include <cuda_fp16.h>
#include <math.h>
#include <stdint.h>
#include <string.h>

#define BB 4
#define CC 64
#define HH 96
#define WW 96
#define NN (HH*WW)
#define HP 48
#define WP 48
#define MM (HP*WP)
#define KD 64
#define OD 64

// ================= scratch =================
__device__ float g_xp [BB*CC*MM];   // pooled x  [b][c][m]  (V source)
__device__ float g_c2p[BB*CC*MM];
__device__ float g_ea [BB*MM];
__device__ float g_kT [BB*MM*KD];   // keys    [b][m][k]
__device__ float g_qT [BB*NN*KD];   // queries [b][n][k]

// ================= helpers =================
__device__ __forceinline__ uint32_t f2tf(float x) {
    uint32_t r;
    asm("cvt.rna.tf32.f32 %0, %1;" : "=r"(r) : "f"(x));
    return r;
}
__device__ __forceinline__ uint32_t pack16(float lo, float hi) {
    __half2 h = __floats2half2_rn(lo, hi);
    uint32_t u;
    memcpy(&u, &h, 4);
    return u;
}
__device__ __forceinline__ void split16(float x, float& hi, float& lo) {
    hi = __half2float(__float2half_rn(x));
    lo = x - hi;
}
// tf32 m16n8k8 (PV)
__device__ __forceinline__ void mma8(float* d, const uint32_t* a, const uint32_t* b) {
    asm volatile("mma.sync.aligned.m16n8k8.row.col.f32.tf32.tf32.f32 "
        "{%0,%1,%2,%3}, {%4,%5,%6,%7}, {%8,%9}, {%0,%1,%2,%3};"
        : "+f"(d[0]), "+f"(d[1]), "+f"(d[2]), "+f"(d[3])
        : "r"(a[0]), "r"(a[1]), "r"(a[2]), "r"(a[3]), "r"(b[0]), "r"(b[1]));
}
// fp16 m16n8k16 (QK)
__device__ __forceinline__ void mma16(float* d, const uint32_t* a, const uint32_t* b) {
    asm volatile("mma.sync.aligned.m16n8k16.row.col.f32.f16.f16.f32 "
        "{%0,%1,%2,%3}, {%4,%5,%6,%7}, {%8,%9}, {%0,%1,%2,%3};"
        : "+f"(d[0]), "+f"(d[1]), "+f"(d[2]), "+f"(d[3])
        : "r"(a[0]), "r"(a[1]), "r"(a[2]), "r"(a[3]), "r"(b[0]), "r"(b[1]));
}

// ================= K1: pool =================
__global__ void pool_kernel(const float* __restrict__ x, const float* __restrict__ c2) {
    int idx = blockIdx.x * blockDim.x + threadIdx.x;
    if (idx >= BB*CC*MM) return;
    int mp = idx % MM;
    int bc = idx / MM;
    int hp = mp / WP, wp = mp % WP;
    int base = (bc*HH + 2*hp)*WW + 2*wp;
    g_xp[idx]  = fmaxf(fmaxf(x[base],  x[base+1]),  fmaxf(x[base+WW],  x[base+WW+1]));
    g_c2p[idx] = fmaxf(fmaxf(c2[base], c2[base+1]), fmaxf(c2[base+WW], c2[base+WW+1]));
}

// ================= K2: edge gate (64 pixels x 2 o-halves) =================
__global__ __launch_bounds__(128) void edge_kernel(
        const float* __restrict__ w_ea1,
        const float* __restrict__ bn_w, const float* __restrict__ bn_b,
        const float* __restrict__ bn_m, const float* __restrict__ bn_v,
        const float* __restrict__ w_ea2, const float* __restrict__ b_ea2) {
    __shared__ __align__(16) float w1t[2*CC*OD];
    __shared__ float scs[OD], bbs[OD], w2s[OD];
    int tid = threadIdx.x;
    for (int i = tid; i < 2*CC*OD; i += 128) {
        int o = i % OD, c = i / OD;
        w1t[i] = w_ea1[o*2*CC + c];
    }
    if (tid < OD) {
        float sc = bn_w[tid] * rsqrtf(bn_v[tid] + 1e-5f);
        scs[tid] = sc;
        bbs[tid] = bn_b[tid] - bn_m[tid]*sc;
        w2s[tid] = w_ea2[tid];
    }
    __syncthreads();
    int half = tid & 1;
    int pix = blockIdx.x * 64 + (tid >> 1);
    int b = pix / MM, mp = pix % MM;
    float h[32];
    #pragma unroll
    for (int i = 0; i < 32; i++) h[i] = 0.f;
    const float* c2p = g_c2p + b*CC*MM + mp;
    const float* xpp = g_xp  + b*CC*MM + mp;
    for (int c = 0; c < 2*CC; c++) {
        float xv = (c < CC) ? c2p[c*MM] : xpp[(c-CC)*MM];
        const float* wr = w1t + c*OD + half*32;
        #pragma unroll
        for (int i = 0; i < 32; i++) h[i] = fmaf(wr[i], xv, h[i]);
    }
    float logit = 0.f;
    #pragma unroll
    for (int i = 0; i < 32; i++) {
        int o = half*32 + i;
        float hv = fmaxf(fmaf(h[i], scs[o], bbs[o]), 0.f);
        logit = fmaf(w2s[o], hv, logit);
    }
    logit += __shfl_xor_sync(0xFFFFFFFFu, logit, 1);
    if (half == 0)
        g_ea[pix] = 1.f / (1.f + expf(-(logit + b_ea2[0])));
}

// ================= K3: 1x1 conv (32 pixels x 4 k-groups) =================
__global__ __launch_bounds__(128) void conv1x1_kernel(
        const float* __restrict__ xin, const float* __restrict__ wq,
        const float* __restrict__ bq, int npix, int is_q) {
    __shared__ __align__(16) float wt[CC*KD];   // [c][k]
    __shared__ __align__(16) float bs[KD];
    int tid = threadIdx.x;
    for (int i = tid; i < CC*KD; i += 128) {
        int k = i % KD, c = i / KD;
        wt[i] = wq[k*CC + c];
    }
    if (tid < KD) bs[tid] = bq[tid];
    __syncthreads();
    int kg = tid >> 5;                          // k-group of 16
    int p  = blockIdx.x * 32 + (tid & 31);
    int b = p / npix, n = p % npix;
    const float* in = is_q ? xin : (const float*)g_xp;
    const float* ip = in + b*CC*npix + n;
    float4 acc[4];
    const float4* bsp = (const float4*)(bs + kg*16);
    #pragma unroll
    for (int i = 0; i < 4; i++) acc[i] = bsp[i];
    for (int c = 0; c < CC; c++) {
        float xv = ip[c*npix];
        const float4* wr = (const float4*)(wt + c*KD + kg*16);
        #pragma unroll
        for (int i = 0; i < 4; i++) {
            float4 wv = wr[i];
            acc[i].x = fmaf(wv.x, xv, acc[i].x);
            acc[i].y = fmaf(wv.y, xv, acc[i].y);
            acc[i].z = fmaf(wv.z, xv, acc[i].z);
            acc[i].w = fmaf(wv.w, xv, acc[i].w);
        }
    }
    float4* op = (float4*)((is_q ? g_qT : g_kT) + (size_t)p*KD + kg*16);
    #pragma unroll
    for (int i = 0; i < 4; i++) op[i] = acc[i];
}

// ================= K4: fp16-QK + tf32-PV flash attention =================
#define TILE 64
#define NT (MM/TILE)        /* 36 */
#define PPAD 68
// word offsets in dynamic smem (uint32/float words)
#define XQH 0               /* Q hi fp16x2 A-frags: 4096 words */
#define XQL 4096            /* Q lo */
#define XKH 8192            /* K hi fp16x2 B-frags: 2048 */
#define XKL 10240
#define XVF 12288           /* V tf32 B-frags: 4096 */
#define XP  16384           /* P plain [128][PPAD]: 8704 floats */
#define XEA (XP + 128*PPAD) /* 25088: 64 floats */
#define SMW (XEA + 64)      /* 25152 words = 100608 B */

__global__ __launch_bounds__(128, 2) void attn_mma_kernel(
        const float* __restrict__ x, const float* __restrict__ gamma,
        float* __restrict__ out) {
    extern __shared__ uint32_t smu[];
    float* smf = (float*)smu;
    float* Psm = smf + XP;
    float* easm = smf + XEA;

    int tid = threadIdx.x;
    int w = tid >> 5, lane = tid & 31;
    int g = lane >> 2, q = lane & 3;
    int b = blockIdx.y;
    int q0 = blockIdx.x * 128;

    // ---- Q fill (once): hi/lo fp16 split into A-fragment layout ----
    #pragma unroll
    for (int i = 0; i < 16; i++) {
        int flat = tid + i*128;                 // 0..2047 float4s
        int row = flat >> 4;
        int j4  = flat & 15;
        int kd0 = j4 * 4;
        float4 v = *(const float4*)(g_qT + ((size_t)(b*NN + q0 + row))*KD + kd0);
        float hx, lx, hy, ly, hz, lz, hw_, lw;
        split16(v.x, hx, lx); split16(v.y, hy, ly);
        split16(v.z, hz, lz); split16(v.w, hw_, lw);
        int ww = row >> 5, m = (row >> 4) & 1, hbit = (row >> 3) & 1, gg = row & 7;
        int kc = kd0 >> 4, rem = kd0 & 15, rsel = rem >> 3, qq = (rem & 7) >> 1;
        int reg = hbit + 2*rsel;
        int base = ((ww*4 + kc)*2 + m)*128;
        smu[XQH + base + (gg*4+qq)*4   + reg] = pack16(hx, hy);
        smu[XQH + base + (gg*4+qq+1)*4 + reg] = pack16(hz, hw_);
        smu[XQL + base + (gg*4+qq)*4   + reg] = pack16(lx, ly);
        smu[XQL + base + (gg*4+qq+1)*4 + reg] = pack16(lz, lw);
    }

    float dacc[8][2][4];
    #pragma unroll
    for (int n = 0; n < 8; n++)
        #pragma unroll
        for (int m = 0; m < 2; m++)
            #pragma unroll
            for (int j = 0; j < 4; j++) dacc[n][m][j] = 0.f;
    float rs[4] = {0.f, 0.f, 0.f, 0.f};

    for (int t = 0; t < NT; t++) {
        int m0 = t * TILE;
        __syncthreads();   // all warps done with prev tile's K/V frags

        // ---- K fill: hi/lo fp16 B-fragments ----
        #pragma unroll
        for (int i = 0; i < 8; i++) {
            int flat = tid + i*128;             // 0..1023
            int key = flat >> 4;
            int kd0 = (flat & 15) * 4;
            float4 v = *(const float4*)(g_kT + ((size_t)(b*MM + m0 + key))*KD + kd0);
            float hx, lx, hy, ly, hz, lz, hw_, lw;
            split16(v.x, hx, lx); split16(v.y, hy, ly);
            split16(v.z, hz, lz); split16(v.w, hw_, lw);
            int n = key >> 3, gg = key & 7;
            int kc = kd0 >> 4, rem = kd0 & 15, r = rem >> 3, qq = (rem & 7) >> 1;
            int base = (kc*8 + n)*64;
            smu[XKH + base + (gg*4+qq)*2   + r] = pack16(hx, hy);
            smu[XKH + base + (gg*4+qq+1)*2 + r] = pack16(hz, hw_);
            smu[XKL + base + (gg*4+qq)*2   + r] = pack16(lx, ly);
            smu[XKL + base + (gg*4+qq+1)*2 + r] = pack16(lz, lw);
        }
        // ---- V fill: tf32 B-fragments ----
        #pragma unroll
        for (int i = 0; i < 8; i++) {
            int flat = tid + i*128;             // 0..1023
            int ch = flat >> 4;
            int key0 = (flat & 15) * 4;
            float4 v = *(const float4*)(g_xp + ((size_t)(b*CC + ch))*MM + m0 + key0);
            int n = ch >> 3, gg = ch & 7;
            int kc = key0 >> 3, r = (key0 & 7) >> 2;
            int base = (kc*8 + n)*64 + gg*8 + r;   // lane=(gg*4+q)*2 + r, q=0..3
            smu[XVF + base + 0] = f2tf(v.x);
            smu[XVF + base + 2] = f2tf(v.y);
            smu[XVF + base + 4] = f2tf(v.z);
            smu[XVF + base + 6] = f2tf(v.w);
        }
        if (tid < TILE) easm[tid] = g_ea[b*MM + m0 + tid];
        __syncthreads();

        // ---- QK: E = Qhi*Khi + Qlo*Khi + Qhi*Klo (fp16 k16) ----
        float eacc[8][2][4];
        #pragma unroll
        for (int n = 0; n < 8; n++)
            #pragma unroll
            for (int m = 0; m < 2; m++)
                #pragma unroll
                for (int j = 0; j < 4; j++) eacc[n][m][j] = 0.f;

        #pragma unroll
        for (int kc = 0; kc < 4; kc++) {
            uint32_t ah[2][4], al[2][4];
            #pragma unroll
            for (int m = 0; m < 2; m++) {
                const uint4* ph = (const uint4*)&smu[XQH + ((w*4+kc)*2+m)*128 + lane*4];
                const uint4* pl = (const uint4*)&smu[XQL + ((w*4+kc)*2+m)*128 + lane*4];
                uint4 vh = *ph, vl = *pl;
                ah[m][0] = vh.x; ah[m][1] = vh.y; ah[m][2] = vh.z; ah[m][3] = vh.w;
                al[m][0] = vl.x; al[m][1] = vl.y; al[m][2] = vl.z; al[m][3] = vl.w;
            }
            #pragma unroll
            for (int n = 0; n < 8; n++) {
                uint32_t bh[2], bl[2];
                uint2 vh = *(const uint2*)&smu[XKH + (kc*8+n)*64 + lane*2];
                uint2 vl = *(const uint2*)&smu[XKL + (kc*8+n)*64 + lane*2];
                bh[0] = vh.x; bh[1] = vh.y;
                bl[0] = vl.x; bl[1] = vl.y;
                #pragma unroll
                for (int m = 0; m < 2; m++) {
                    mma16(eacc[n][m], ah[m], bh);
                    mma16(eacc[n][m], al[m], bh);
                    mma16(eacc[n][m], ah[m], bl);
                }
            }
        }

        // ---- softmax (no max-shift) + P store (tf32) ----
        #pragma unroll
        for (int n = 0; n < 8; n++) {
            float2 ea2 = *(float2*)(easm + n*8 + 2*q);
            #pragma unroll
            for (int m = 0; m < 2; m++) {
                float p0 = __expf(eacc[n][m][0] * ea2.x);
                float p1 = __expf(eacc[n][m][1] * ea2.y);
                float p2 = __expf(eacc[n][m][2] * ea2.x);
                float p3 = __expf(eacc[n][m][3] * ea2.y);
                rs[m*2+0] += p0 + p1;
                rs[m*2+1] += p2 + p3;
                int r = w*32 + m*16 + g;
                *(uint2*)(Psm + r*PPAD     + n*8 + 2*q) = make_uint2(f2tf(p0), f2tf(p1));
                *(uint2*)(Psm + (r+8)*PPAD + n*8 + 2*q) = make_uint2(f2tf(p2), f2tf(p3));
            }
        }
        __syncwarp();

        // ---- PV: D += P * V (tf32 k8) ----
        #pragma unroll
        for (int kc = 0; kc < 8; kc++) {
            uint32_t pa[2][4];
            #pragma unroll
            for (int m = 0; m < 2; m++) {
                int r = w*32 + m*16 + g;
                pa[m][0] = __float_as_uint(Psm[r*PPAD     + kc*8 + q]);
                pa[m][1] = __float_as_uint(Psm[(r+8)*PPAD + kc*8 + q]);
                pa[m][2] = __float_as_uint(Psm[r*PPAD     + kc*8 + q + 4]);
                pa[m][3] = __float_as_uint(Psm[(r+8)*PPAD + kc*8 + q + 4]);
            }
            #pragma unroll
            for (int n = 0; n < 8; n++) {
                uint32_t vb[2];
                uint2 vv = *(const uint2*)&smu[XVF + (kc*8+n)*64 + lane*2];
                vb[0] = vv.x; vb[1] = vv.y;
                #pragma unroll
                for (int m = 0; m < 2; m++) mma8(dacc[n][m], pa[m], vb);
            }
        }
    }

    // ---- epilogue: quad-reduce row sums, normalize, residual add ----
    #pragma unroll
    for (int i = 0; i < 4; i++) {
        rs[i] += __shfl_xor_sync(0xFFFFFFFFu, rs[i], 1);
        rs[i] += __shfl_xor_sync(0xFFFFFFFFu, rs[i], 2);
    }
    float gm = gamma[0];
    float invA0 = gm / rs[0], invB0 = gm / rs[1];
    float invA1 = gm / rs[2], invB1 = gm / rs[3];
    #pragma unroll
    for (int n = 0; n < 8; n++) {
        #pragma unroll
        for (int m = 0; m < 2; m++) {
            int ch = n*8 + 2*q;
            int r  = w*32 + m*16 + g;
            float ia = m ? invA1 : invA0;
            float ib = m ? invB1 : invB0;
            size_t o00 = ((size_t)(b*CC + ch))*NN + q0 + r;
            size_t o01 = o00 + NN;
            size_t o10 = o00 + 8;
            size_t o11 = o01 + 8;
            out[o00] = fmaf(dacc[n][m][0], ia, x[o00]);
            out[o01] = fmaf(dacc[n][m][1], ia, x[o01]);
            out[o10] = fmaf(dacc[n][m][2], ib, x[o10]);
            out[o11] = fmaf(dacc[n][m][3], ib, x[o11]);
        }
    }
}

// ================= launch =================
extern "C" void kernel_launch(void* const* d_in, const int* in_sizes, int n_in,
                              void* d_out, int out_size) {
    const float* c2    = (const float*)d_in[0];
    const float* x     = (const float*)d_in[1];
    const float* w_ea1 = (const float*)d_in[2];
    const float* bn_w  = (const float*)d_in[3];
    const float* bn_b  = (const float*)d_in[4];
    const float* bn_m  = (const float*)d_in[5];
    const float* bn_v  = (const float*)d_in[6];
    const float* w_ea2 = (const float*)d_in[7];
    const float* b_ea2 = (const float*)d_in[8];
    const float* w_q   = (const float*)d_in[9];
    const float* b_q   = (const float*)d_in[10];
    const float* gamma = (const float*)d_in[11];
    float* out = (float*)d_out;

    cudaFuncSetAttribute(attn_mma_kernel,
                         cudaFuncAttributeMaxDynamicSharedMemorySize, SMW*4);

    pool_kernel<<<(BB*CC*MM + 255)/256, 256>>>(x, c2);
    edge_kernel<<<(BB*MM)/64, 128>>>(w_ea1, bn_w, bn_b, bn_m, bn_v, w_ea2, b_ea2);
    conv1x1_kernel<<<(BB*NN)/32, 128>>>(x, w_q, b_q, NN, 1);
    conv1x1_kernel<<<(BB*MM)/32, 128>>>(x, w_q, b_q, MM, 0);
    attn_mma_kernel<<<dim3(NN/128, BB), 128, SMW*4>>>(x, gamma, out);
}

// round 11
// speedup vs baseline: 3.7120x; 1.3347x over previous
#include <cuda_runtime.h>
#include <cuda_fp16.h>
#include <math.h>
#include <stdint.h>
#include <string.h>

#define BB 4
#define CC 64
#define HH 96
#define WW 96
#define NN (HH*WW)
#define HP 48
#define WP 48
#define MM (HP*WP)
#define KD 64
#define OD 64
#define TILE 64
#define NT (MM/TILE)        /* 36 */

// ================= scratch =================
__device__ float g_xp [BB*CC*MM];   // pooled x  [b][c][m]
__device__ float g_c2p[BB*CC*MM];
__device__ float g_ea [BB*MM];
__device__ float g_kT [BB*MM*KD];   // keys    [b][m][k]
__device__ float g_qT [BB*NN*KD];   // queries [b][n][k]
__device__ uint32_t g_frag[BB*NT*3*2048];  // per (b,t): Khi | Klo | Vf fragment images

// ================= helpers =================
__device__ __forceinline__ uint32_t pack16(float lo, float hi) {
    __half2 h = __floats2half2_rn(lo, hi);
    uint32_t u;
    memcpy(&u, &h, 4);
    return u;
}
__device__ __forceinline__ void split16(float x, float& hi, float& lo) {
    hi = __half2float(__float2half_rn(x));
    lo = x - hi;
}
__device__ __forceinline__ void mma16(float* d, const uint32_t* a, const uint32_t* b) {
    asm volatile("mma.sync.aligned.m16n8k16.row.col.f32.f16.f16.f32 "
        "{%0,%1,%2,%3}, {%4,%5,%6,%7}, {%8,%9}, {%0,%1,%2,%3};"
        : "+f"(d[0]), "+f"(d[1]), "+f"(d[2]), "+f"(d[3])
        : "r"(a[0]), "r"(a[1]), "r"(a[2]), "r"(a[3]), "r"(b[0]), "r"(b[1]));
}

// ================= K1: pool =================
__global__ void pool_kernel(const float* __restrict__ x, const float* __restrict__ c2) {
    int idx = blockIdx.x * blockDim.x + threadIdx.x;
    if (idx >= BB*CC*MM) return;
    int mp = idx % MM;
    int bc = idx / MM;
    int hp = mp / WP, wp = mp % WP;
    int base = (bc*HH + 2*hp)*WW + 2*wp;
    g_xp[idx]  = fmaxf(fmaxf(x[base],  x[base+1]),  fmaxf(x[base+WW],  x[base+WW+1]));
    g_c2p[idx] = fmaxf(fmaxf(c2[base], c2[base+1]), fmaxf(c2[base+WW], c2[base+WW+1]));
}

// ================= K2: edge gate =================
__global__ __launch_bounds__(128) void edge_kernel(
        const float* __restrict__ w_ea1,
        const float* __restrict__ bn_w, const float* __restrict__ bn_b,
        const float* __restrict__ bn_m, const float* __restrict__ bn_v,
        const float* __restrict__ w_ea2, const float* __restrict__ b_ea2) {
    __shared__ __align__(16) float w1t[2*CC*OD];
    __shared__ float scs[OD], bbs[OD], w2s[OD];
    int tid = threadIdx.x;
    for (int i = tid; i < 2*CC*OD; i += 128) {
        int o = i % OD, c = i / OD;
        w1t[i] = w_ea1[o*2*CC + c];
    }
    if (tid < OD) {
        float sc = bn_w[tid] * rsqrtf(bn_v[tid] + 1e-5f);
        scs[tid] = sc;
        bbs[tid] = bn_b[tid] - bn_m[tid]*sc;
        w2s[tid] = w_ea2[tid];
    }
    __syncthreads();
    int half = tid & 1;
    int pix = blockIdx.x * 64 + (tid >> 1);
    int b = pix / MM, mp = pix % MM;
    float h[32];
    #pragma unroll
    for (int i = 0; i < 32; i++) h[i] = 0.f;
    const float* c2p = g_c2p + b*CC*MM + mp;
    const float* xpp = g_xp  + b*CC*MM + mp;
    for (int c = 0; c < 2*CC; c++) {
        float xv = (c < CC) ? c2p[c*MM] : xpp[(c-CC)*MM];
        const float* wr = w1t + c*OD + half*32;
        #pragma unroll
        for (int i = 0; i < 32; i++) h[i] = fmaf(wr[i], xv, h[i]);
    }
    float logit = 0.f;
    #pragma unroll
    for (int i = 0; i < 32; i++) {
        int o = half*32 + i;
        float hv = fmaxf(fmaf(h[i], scs[o], bbs[o]), 0.f);
        logit = fmaf(w2s[o], hv, logit);
    }
    logit += __shfl_xor_sync(0xFFFFFFFFu, logit, 1);
    if (half == 0)
        g_ea[pix] = 1.f / (1.f + expf(-(logit + b_ea2[0])));
}

// ================= K3: 1x1 conv =================
__global__ __launch_bounds__(128) void conv1x1_kernel(
        const float* __restrict__ xin, const float* __restrict__ wq,
        const float* __restrict__ bq, int npix, int is_q) {
    __shared__ __align__(16) float wt[CC*KD];
    __shared__ __align__(16) float bs[KD];
    int tid = threadIdx.x;
    for (int i = tid; i < CC*KD; i += 128) {
        int k = i % KD, c = i / KD;
        wt[i] = wq[k*CC + c];
    }
    if (tid < KD) bs[tid] = bq[tid];
    __syncthreads();
    int kg = tid >> 5;
    int p  = blockIdx.x * 32 + (tid & 31);
    int b = p / npix, n = p % npix;
    const float* in = is_q ? xin : (const float*)g_xp;
    const float* ip = in + b*CC*npix + n;
    float4 acc[4];
    const float4* bsp = (const float4*)(bs + kg*16);
    #pragma unroll
    for (int i = 0; i < 4; i++) acc[i] = bsp[i];
    for (int c = 0; c < CC; c++) {
        float xv = ip[c*npix];
        const float4* wr = (const float4*)(wt + c*KD + kg*16);
        #pragma unroll
        for (int i = 0; i < 4; i++) {
            float4 wv = wr[i];
            acc[i].x = fmaf(wv.x, xv, acc[i].x);
            acc[i].y = fmaf(wv.y, xv, acc[i].y);
            acc[i].z = fmaf(wv.z, xv, acc[i].z);
            acc[i].w = fmaf(wv.w, xv, acc[i].w);
        }
    }
    float4* op = (float4*)((is_q ? g_qT : g_kT) + (size_t)p*KD + kg*16);
    #pragma unroll
    for (int i = 0; i < 4; i++) op[i] = acc[i];
}

// ================= K3b: fragment prep (K hi/lo fp16 + V fp16) ============
__global__ __launch_bounds__(128) void frag_prep_kernel() {
    int t = blockIdx.x, b = blockIdx.y;
    int tid = threadIdx.x;
    uint32_t* kh = g_frag + ((size_t)(b*NT + t)*3 + 0)*2048;
    uint32_t* kl = g_frag + ((size_t)(b*NT + t)*3 + 1)*2048;
    uint32_t* vf = g_frag + ((size_t)(b*NT + t)*3 + 2)*2048;
    // K hi/lo fragments
    #pragma unroll
    for (int i = 0; i < 8; i++) {
        int flat = tid + i*128;                  // 0..1023 float4s
        int key = flat >> 4;
        int kd0 = (flat & 15) * 4;
        float4 v = *(const float4*)(g_kT + ((size_t)(b*MM + t*TILE + key))*KD + kd0);
        float hx, lx, hy, ly, hz, lz, hw, lw;
        split16(v.x, hx, lx); split16(v.y, hy, ly);
        split16(v.z, hz, lz); split16(v.w, hw, lw);
        int n = key >> 3, g = key & 7;
        int kc = kd0 >> 4, rem = kd0 & 15, r = rem >> 3, q = (rem & 7) >> 1;
        int w0 = (kc*8 + n)*64 + (g*4 + q)*2 + r;
        int w1 = (kc*8 + n)*64 + (g*4 + q + 1)*2 + r;
        kh[w0] = pack16(hx, hy); kh[w1] = pack16(hz, hw);
        kl[w0] = pack16(lx, ly); kl[w1] = pack16(lz, lw);
    }
    // V fragments
    #pragma unroll
    for (int i = 0; i < 16; i++) {
        int w = tid + i*128;                     // 0..2047 words
        int r = w & 1;
        int gq = (w >> 1) & 31;
        int g = gq >> 2, q = gq & 3;
        int kn = w >> 6;
        int kc = kn >> 3, n = kn & 7;
        int ch = n*8 + g;
        int key = kc*16 + r*8 + 2*q;
        float2 v = *(const float2*)(g_xp + ((size_t)(b*CC + ch))*MM + t*TILE + key);
        vf[w] = pack16(v.x, v.y);
    }
}

// ================= K4: flash attention, register P =================
// SMEM word map
#define XQH 0               /* Q hi fp16 A-frags: 4096 words */
#define XQL 4096
#define XKH 8192            /* K hi B-frags: 2048 */
#define XKL 10240
#define XVF 12288           /* V fp16 B-frags: 2048 */
#define XEA 14336           /* 64 floats */
#define SMW 14400           /* 57600 bytes */

__global__ __launch_bounds__(128, 2) void attn_mma_kernel(
        const float* __restrict__ x, const float* __restrict__ gamma,
        float* __restrict__ out) {
    extern __shared__ uint32_t smu[];
    float* easm = (float*)(smu + XEA);

    int tid = threadIdx.x;
    int w = tid >> 5, lane = tid & 31;
    int g = lane >> 2, q = lane & 3;
    int b = blockIdx.y;
    int q0 = blockIdx.x * 128;

    // ---- Q fill (once): hi/lo fp16 split into A-fragment layout ----
    #pragma unroll
    for (int i = 0; i < 16; i++) {
        int flat = tid + i*128;
        int row = flat >> 4;
        int kd0 = (flat & 15) * 4;
        float4 v = *(const float4*)(g_qT + ((size_t)(b*NN + q0 + row))*KD + kd0);
        float hx, lx, hy, ly, hz, lz, hw_, lw;
        split16(v.x, hx, lx); split16(v.y, hy, ly);
        split16(v.z, hz, lz); split16(v.w, hw_, lw);
        int ww = row >> 5, m = (row >> 4) & 1, hbit = (row >> 3) & 1, gg = row & 7;
        int kc = kd0 >> 4, rem = kd0 & 15, rsel = rem >> 3, qq = (rem & 7) >> 1;
        int reg = hbit + 2*rsel;
        int base = ((ww*4 + kc)*2 + m)*128;
        smu[XQH + base + (gg*4+qq)*4   + reg] = pack16(hx, hy);
        smu[XQH + base + (gg*4+qq+1)*4 + reg] = pack16(hz, hw_);
        smu[XQL + base + (gg*4+qq)*4   + reg] = pack16(lx, ly);
        smu[XQL + base + (gg*4+qq+1)*4 + reg] = pack16(lz, lw);
    }

    float dacc[8][2][4];
    #pragma unroll
    for (int n = 0; n < 8; n++)
        #pragma unroll
        for (int m = 0; m < 2; m++)
            #pragma unroll
            for (int j = 0; j < 4; j++) dacc[n][m][j] = 0.f;
    float mx[4] = {-1e30f, -1e30f, -1e30f, -1e30f};
    float rs[4] = {0.f, 0.f, 0.f, 0.f};

    const uint4* fsrc = (const uint4*)(g_frag + (size_t)b*NT*3*2048);

    for (int t = 0; t < NT; t++) {
        __syncthreads();   // prev tile readers done

        // ---- fill: copy precomputed fragment image (Khi|Klo|Vf = 1536 uint4) ----
        {
            const uint4* src = fsrc + (size_t)t*1536;
            uint4* dst = (uint4*)(smu + XKH);
            #pragma unroll
            for (int i = 0; i < 12; i++) dst[tid + i*128] = src[tid + i*128];
            if (tid < TILE) easm[tid] = g_ea[b*MM + t*TILE + tid];
        }
        __syncthreads();

        // ---- QK: E = Qhi*Khi + Qlo*Khi + Qhi*Klo (fp16 k16) ----
        float eacc[8][2][4];
        #pragma unroll
        for (int n = 0; n < 8; n++)
            #pragma unroll
            for (int m = 0; m < 2; m++)
                #pragma unroll
                for (int j = 0; j < 4; j++) eacc[n][m][j] = 0.f;

        #pragma unroll
        for (int kc = 0; kc < 4; kc++) {
            uint32_t ah[2][4], al[2][4];
            #pragma unroll
            for (int m = 0; m < 2; m++) {
                uint4 vh = *(const uint4*)&smu[XQH + ((w*4+kc)*2+m)*128 + lane*4];
                uint4 vl = *(const uint4*)&smu[XQL + ((w*4+kc)*2+m)*128 + lane*4];
                ah[m][0] = vh.x; ah[m][1] = vh.y; ah[m][2] = vh.z; ah[m][3] = vh.w;
                al[m][0] = vl.x; al[m][1] = vl.y; al[m][2] = vl.z; al[m][3] = vl.w;
            }
            #pragma unroll
            for (int n = 0; n < 8; n++) {
                uint32_t bh[2], bl[2];
                uint2 vh = *(const uint2*)&smu[XKH + (kc*8+n)*64 + lane*2];
                uint2 vl = *(const uint2*)&smu[XKL + (kc*8+n)*64 + lane*2];
                bh[0] = vh.x; bh[1] = vh.y;
                bl[0] = vl.x; bl[1] = vl.y;
                #pragma unroll
                for (int m = 0; m < 2; m++) {
                    mma16(eacc[n][m], ah[m], bh);
                    mma16(eacc[n][m], al[m], bh);
                    mma16(eacc[n][m], ah[m], bl);
                }
            }
        }

        // ---- ea scale + tile row-max ----
        float tm[4] = {-1e30f, -1e30f, -1e30f, -1e30f};
        #pragma unroll
        for (int n = 0; n < 8; n++) {
            float2 ea2 = *(float2*)(easm + n*8 + 2*q);
            #pragma unroll
            for (int m = 0; m < 2; m++) {
                float e0 = eacc[n][m][0] * ea2.x;
                float e1 = eacc[n][m][1] * ea2.y;
                float e2 = eacc[n][m][2] * ea2.x;
                float e3 = eacc[n][m][3] * ea2.y;
                eacc[n][m][0] = e0; eacc[n][m][1] = e1;
                eacc[n][m][2] = e2; eacc[n][m][3] = e3;
                tm[2*m]   = fmaxf(tm[2*m],   fmaxf(e0, e1));
                tm[2*m+1] = fmaxf(tm[2*m+1], fmaxf(e2, e3));
            }
        }
        #pragma unroll
        for (int i = 0; i < 4; i++) {
            tm[i] = fmaxf(tm[i], __shfl_xor_sync(0xFFFFFFFFu, tm[i], 1));
            tm[i] = fmaxf(tm[i], __shfl_xor_sync(0xFFFFFFFFu, tm[i], 2));
        }
        float scal[4];
        #pragma unroll
        for (int i = 0; i < 4; i++) {
            float mn = fmaxf(mx[i], tm[i]);
            scal[i] = __expf(mx[i] - mn);
            mx[i] = mn;
            rs[i] *= scal[i];
        }
        #pragma unroll
        for (int n = 0; n < 8; n++)
            #pragma unroll
            for (int m = 0; m < 2; m++) {
                dacc[n][m][0] *= scal[2*m];   dacc[n][m][1] *= scal[2*m];
                dacc[n][m][2] *= scal[2*m+1]; dacc[n][m][3] *= scal[2*m+1];
            }

        // ---- softmax exp + pack P into fp16 A-fragments (registers) ----
        uint32_t pf[4][2][4];
        #pragma unroll
        for (int n = 0; n < 8; n++) {
            int kc = n >> 1, hf = n & 1;
            #pragma unroll
            for (int m = 0; m < 2; m++) {
                float p0 = __expf(eacc[n][m][0] - mx[2*m]);
                float p1 = __expf(eacc[n][m][1] - mx[2*m]);
                float p2 = __expf(eacc[n][m][2] - mx[2*m+1]);
                float p3 = __expf(eacc[n][m][3] - mx[2*m+1]);
                rs[2*m]   += p0 + p1;
                rs[2*m+1] += p2 + p3;
                pf[kc][m][2*hf]   = pack16(p0, p1);
                pf[kc][m][2*hf+1] = pack16(p2, p3);
            }
        }

        // ---- PV: D += P * V (fp16 k16, P from registers) ----
        #pragma unroll
        for (int kc = 0; kc < 4; kc++) {
            #pragma unroll
            for (int n = 0; n < 8; n++) {
                uint32_t vb[2];
                uint2 vv = *(const uint2*)&smu[XVF + (kc*8+n)*64 + lane*2];
                vb[0] = vv.x; vb[1] = vv.y;
                #pragma unroll
                for (int m = 0; m < 2; m++) mma16(dacc[n][m], pf[kc][m], vb);
            }
        }
    }

    // ---- epilogue ----
    #pragma unroll
    for (int i = 0; i < 4; i++) {
        rs[i] += __shfl_xor_sync(0xFFFFFFFFu, rs[i], 1);
        rs[i] += __shfl_xor_sync(0xFFFFFFFFu, rs[i], 2);
    }
    float gm = gamma[0];
    float invA0 = gm / rs[0], invB0 = gm / rs[1];
    float invA1 = gm / rs[2], invB1 = gm / rs[3];
    #pragma unroll
    for (int n = 0; n < 8; n++) {
        #pragma unroll
        for (int m = 0; m < 2; m++) {
            int ch = n*8 + 2*q;
            int r  = w*32 + m*16 + g;
            float ia = m ? invA1 : invA0;
            float ib = m ? invB1 : invB0;
            size_t o00 = ((size_t)(b*CC + ch))*NN + q0 + r;
            size_t o01 = o00 + NN;
            size_t o10 = o00 + 8;
            size_t o11 = o01 + 8;
            out[o00] = fmaf(dacc[n][m][0], ia, x[o00]);
            out[o01] = fmaf(dacc[n][m][1], ia, x[o01]);
            out[o10] = fmaf(dacc[n][m][2], ib, x[o10]);
            out[o11] = fmaf(dacc[n][m][3], ib, x[o11]);
        }
    }
}

// ================= launch =================
extern "C" void kernel_launch(void* const* d_in, const int* in_sizes, int n_in,
                              void* d_out, int out_size) {
    const float* c2    = (const float*)d_in[0];
    const float* x     = (const float*)d_in[1];
    const float* w_ea1 = (const float*)d_in[2];
    const float* bn_w  = (const float*)d_in[3];
    const float* bn_b  = (const float*)d_in[4];
    const float* bn_m  = (const float*)d_in[5];
    const float* bn_v  = (const float*)d_in[6];
    const float* w_ea2 = (const float*)d_in[7];
    const float* b_ea2 = (const float*)d_in[8];
    const float* w_q   = (const float*)d_in[9];
    const float* b_q   = (const float*)d_in[10];
    const float* gamma = (const float*)d_in[11];
    float* out = (float*)d_out;

    cudaFuncSetAttribute(attn_mma_kernel,
                         cudaFuncAttributeMaxDynamicSharedMemorySize, SMW*4);

    pool_kernel<<<(BB*CC*MM + 255)/256, 256>>>(x, c2);
    edge_kernel<<<(BB*MM)/64, 128>>>(w_ea1, bn_w, bn_b, bn_m, bn_v, w_ea2, b_ea2);
    conv1x1_kernel<<<(BB*NN)/32, 128>>>(x, w_q, b_q, NN, 1);
    conv1x1_kernel<<<(BB*MM)/32, 128>>>(x, w_q, b_q, MM, 0);
    frag_prep_kernel<<<dim3(NT, BB), 128>>>();
    attn_mma_kernel<<<dim3(NN/128, BB), 128, SMW*4>>>(x, gamma, out);
}